// round 15
// baseline (speedup 1.0000x reference)
#include <cuda_runtime.h>

#define NN 100000
#define NE 300000
#define NB 1024
#define NW 3136           // bitmask words (ceil(NN/32), padded)
#define EB 1172           // edge blocks ((NE+255)/256)
#define NBK 391           // node blocks ((NN+255)/256)

// ---- PDL primitives (sm_90+) ----
__device__ __forceinline__ void gdep_launch() {
    asm volatile("griddepcontrol.launch_dependents;");
}
__device__ __forceinline__ void gdep_wait() {
    asm volatile("griddepcontrol.wait;" ::: "memory");
}

// ---- warp-aggregated slot allocation: returns this lane's slot (valid if emit) ----
__device__ __forceinline__ int warp_alloc(int* counter, bool emit) {
    unsigned m = __ballot_sync(0xFFFFFFFFu, emit);
    if (!m) return -1;
    int lane = threadIdx.x & 31;
    int leader = __ffs(m) - 1;
    int base = 0;
    if (lane == leader) base = atomicAdd(counter, __popc(m));
    base = __shfl_sync(0xFFFFFFFFu, base, leader);
    return base + __popc(m & ((1u << lane) - 1));
}

// ---------------- device scratch (static, 16B-aligned via float4) ----------------
__device__ float4 g_vs4[NN];              // positions padded to float4
__device__ float4 g_agg0[NN];             // position agg
__device__ float4 g_agg1[NN * 16];        // layer1 agg, compact by slot1
__device__ float4 g_agg2[NB * 32];        // layer2 agg, compact by slot2
__device__ float4 g_x1[NN * 16];          // layer0 out (written only where needed)
__device__ float4 g_x2c[NN * 32];         // layer1 out, compact by slot1
__device__ unsigned g_bmB[NW];            // boundary bitmask
__device__ unsigned g_bmN1[NW];           // N1 bitmask
__device__ unsigned g_bmN2[NW];           // after pass2c: "x1 needed" = N1 | N2
__device__ int g_slot1[NN];
__device__ int g_slot2[NN];
__device__ int g_list1[NN];               // slot1 -> node
__device__ int2 g_e1[NE];                 // active layer1 edges
__device__ int2 g_e2[NE];                 // active layer2 edges
__device__ int g_cnt1, g_cntE1, g_cntE2, g_done, g_done0;
__device__ float g_pool[256];
__device__ float g_bsum[3];

__device__ __forceinline__ int bm_get(const unsigned* bm, int n) {
    return (bm[n >> 5] >> (n & 31)) & 1;
}
__device__ __forceinline__ void bm_set(unsigned* bm, int n) {
    atomicOr(&bm[n >> 5], 1u << (n & 31));
}

// ---------------- init (+ last-block markB fusion) ----------------
__global__ void k_init(const float* __restrict__ vs, const int* __restrict__ bidx) {
    gdep_launch();
    int i = blockIdx.x * 256 + threadIdx.x;
    int tid = threadIdx.x;
    float4 z = make_float4(0.f, 0.f, 0.f, 0.f);
    if (i < NN) {
        g_agg0[i] = z;
        g_vs4[i] = make_float4(vs[3 * i], vs[3 * i + 1], vs[3 * i + 2], 0.f);
    }
    if (i < NW) { g_bmB[i] = 0; g_bmN1[i] = 0; g_bmN2[i] = 0; }
    if (i < NB * 32) g_agg2[i] = z;
    if (i < 256) g_pool[i] = 0.f;
    if (i < 3) g_bsum[i] = 0.f;
    if (i == 0) { g_cnt1 = 0; g_cntE1 = 0; g_cntE2 = 0; g_done = 0; }
    __shared__ int lastFlag;
    __threadfence();
    __syncthreads();
    if (tid == 0) lastFlag = (atomicAdd(&g_done0, 1) == NBK - 1);
    __syncthreads();
    if (!lastFlag) return;
    if (tid == 0) g_done0 = 0;            // self-reset for graph replay
    float s0 = 0.f, s1 = 0.f, s2 = 0.f;
    for (int j = tid; j < NB; j += 256) {
        int n = bidx[j];
        bm_set(g_bmB, n); bm_set(g_bmN1, n);
        g_slot2[n] = j;
        s0 += vs[3 * n]; s1 += vs[3 * n + 1]; s2 += vs[3 * n + 2];
    }
    atomicAdd(&g_bsum[0], s0);
    atomicAdd(&g_bsum[1], s1);
    atomicAdd(&g_bsum[2], s2);
}

// ---------------- pass 1: position agg + N1 mark + e2 emit (warp-agg counter) ----------------
__global__ void k_pass1(const int* __restrict__ edges) {
    gdep_launch();
    int e = blockIdx.x * 256 + threadIdx.x;
    bool val = e < NE;
    int s = 0, d = 0;
    if (val) { s = edges[2 * e]; d = edges[2 * e + 1]; }   // inputs: pre-wait
    gdep_wait();
    int bs = 0, bd = 0;
    if (val) {
        float4 ps = g_vs4[s];
        float4 pd = g_vs4[d];
        atomicAdd(&g_agg0[d], ps);
        atomicAdd(&g_agg0[s], pd);
        bs = bm_get(g_bmB, s); bd = bm_get(g_bmB, d);
    }
    bool emit = val && (bs | bd);
    int pos = warp_alloc(&g_cntE2, emit);
    if (emit) {
        if (bd) bm_set(g_bmN1, s);
        if (bs) bm_set(g_bmN1, d);
        g_e2[pos] = make_int2(s | (bs << 30), d | (bd << 30));
    }
}

// ---------------- pass 2 (+ slot1 compaction in tail; tail ORs N1 into N2) ----------------
__global__ void k_pass2c(const int* __restrict__ edges) {
    gdep_launch();
    int bid = blockIdx.x;
    if (bid < EB) {
        int e = bid * 256 + threadIdx.x;
        bool val = e < NE;
        int s = 0, d = 0;
        if (val) { s = edges[2 * e]; d = edges[2 * e + 1]; }   // pre-wait
        gdep_wait();
        int as = 0, ad = 0;
        if (val) { as = bm_get(g_bmN1, s); ad = bm_get(g_bmN1, d); }
        bool emit = val && (as | ad);
        int pos = warp_alloc(&g_cntE1, emit);
        if (emit) {
            if (ad) bm_set(g_bmN2, s);
            if (as) bm_set(g_bmN2, d);
            g_e1[pos] = make_int2(s | (as << 30), d | (ad << 30));
        }
    } else {
        gdep_wait();
        int i = (bid - EB) * 256 + threadIdx.x;
        bool inb = i < NN;
        if (inb && (i & 31) == 0) {
            unsigned w = g_bmN1[i >> 5];
            if (w) atomicOr(&g_bmN2[i >> 5], w);
        }
        bool act = inb && bm_get(g_bmN1, i);
        int p = warp_alloc(&g_cnt1, act);
        if (act) {
            g_slot1[i] = p; g_list1[p] = i;
            float4 z = make_float4(0.f, 0.f, 0.f, 0.f);
#pragma unroll
            for (int c = 0; c < 16; c++) g_agg1[p * 16 + c] = z;
        }
    }
}

// ---------------- layer 0 node update: one warp per bitmask word; weights preloaded pre-wait ----------------
__global__ void k_node0(const float* __restrict__ Ws, const float* __restrict__ Wn,
                        const float* __restrict__ b) {
    gdep_launch();
    int wid = (blockIdx.x * 256 + threadIdx.x) >> 5;
    int lane = threadIdx.x & 31;
    int half = lane >> 4;
    int c4 = lane & 15;
    float4 w0 = ((const float4*)Ws)[c4];
    float4 w1 = ((const float4*)(Ws + 64))[c4];
    float4 w2 = ((const float4*)(Ws + 128))[c4];
    float4 n0 = ((const float4*)Wn)[c4];
    float4 n1 = ((const float4*)(Wn + 64))[c4];
    float4 n2 = ((const float4*)(Wn + 128))[c4];
    float4 bb = ((const float4*)b)[c4];
    gdep_wait();
    if (wid >= NW) return;
    unsigned w = g_bmN2[wid];
    if (!w) return;
    int base = wid << 5;
    unsigned mywork = w;
    int idx = 0;
    while (mywork) {
        int bit = __ffs(mywork) - 1;
        mywork &= mywork - 1;
        if ((idx++ & 1) != half) continue;
        int node = base + bit;
        float4 p = g_vs4[node];
        float4 a = g_agg0[node];
        float4 r;
        r.x = fmaxf(bb.x + p.x*w0.x + p.y*w1.x + p.z*w2.x + a.x*n0.x + a.y*n1.x + a.z*n2.x, 0.f);
        r.y = fmaxf(bb.y + p.x*w0.y + p.y*w1.y + p.z*w2.y + a.x*n0.y + a.y*n1.y + a.z*n2.y, 0.f);
        r.z = fmaxf(bb.z + p.x*w0.z + p.y*w1.z + p.z*w2.z + a.x*n0.z + a.y*n1.z + a.z*n2.z, 0.f);
        r.w = fmaxf(bb.w + p.x*w0.w + p.y*w1.w + p.z*w2.w + a.x*n0.w + a.y*n1.w + a.z*n2.w, 0.f);
        g_x1[node * 16 + c4] = r;
    }
}

// ---------------- layer 1 edge aggregation ----------------
__global__ void k_edge1() {
    gdep_launch();
    gdep_wait();
    int tot = g_cntE1 << 4;
    int stride = gridDim.x * blockDim.x;
    for (int t = blockIdx.x * blockDim.x + threadIdx.x; t < tot; t += stride) {
        int ei = t >> 4, c4 = t & 15;
        int2 en = g_e1[ei];
        int s = en.x & 0x3FFFFFFF, sa = (unsigned)en.x >> 30;
        int d = en.y & 0x3FFFFFFF, da = (unsigned)en.y >> 30;
        if (da) atomicAdd(&g_agg1[g_slot1[d] * 16 + c4], g_x1[s * 16 + c4]);
        if (sa) atomicAdd(&g_agg1[g_slot1[s] * 16 + c4], g_x1[d * 16 + c4]);
    }
}

// ---------------- layer 1 node update: weights staged pre-wait ----------------
__global__ void k_node1(const float* __restrict__ Ws, const float* __restrict__ Wn,
                        const float* __restrict__ b) {
    gdep_launch();
    extern __shared__ float sm[];
    float* sWs = sm;            // 64*128
    float* sWn = sm + 8192;
    __shared__ float xs[2][64], as[2][64];
    int tid = threadIdx.x;
    int pair = tid >> 7, c = tid & 127;
    for (int i = tid; i < 8192; i += 256) { sWs[i] = Ws[i]; sWn[i] = Wn[i]; }
    float bc = b[c];
    gdep_wait();
    __syncthreads();
    int cnt = g_cnt1;
    for (int slot0 = blockIdx.x * 2; slot0 < cnt; slot0 += gridDim.x * 2) {
        int slot = slot0 + pair;
        bool act = slot < cnt;
        if (act && c < 128) {
            int node = g_list1[slot];
            if (c < 64) xs[pair][c] = ((const float*)g_x1)[node * 64 + c];
            else        as[pair][c - 64] = ((const float*)g_agg1)[slot * 64 + (c - 64)];
        }
        __syncthreads();
        if (act) {
            float acc = bc;
#pragma unroll 16
            for (int k = 0; k < 64; k++)
                acc += xs[pair][k] * sWs[k * 128 + c] + as[pair][k] * sWn[k * 128 + c];
            ((float*)g_x2c)[slot * 128 + c] = fmaxf(acc, 0.f);
        }
        __syncthreads();
    }
}

// ---------------- layer 2 edge aggregation ----------------
__global__ void k_edge2() {
    gdep_launch();
    gdep_wait();
    int tot = g_cntE2 << 5;
    int stride = gridDim.x * blockDim.x;
    for (int t = blockIdx.x * blockDim.x + threadIdx.x; t < tot; t += stride) {
        int ei = t >> 5, c4 = t & 31;
        int2 en = g_e2[ei];
        int s = en.x & 0x3FFFFFFF, bs = (unsigned)en.x >> 30;
        int d = en.y & 0x3FFFFFFF, bd = (unsigned)en.y >> 30;
        if (bd) atomicAdd(&g_agg2[g_slot2[d] * 32 + c4], g_x2c[g_slot1[s] * 32 + c4]);
        if (bs) atomicAdd(&g_agg2[g_slot2[s] * 32 + c4], g_x2c[g_slot1[d] * 32 + c4]);
    }
}

// ---------------- layer 2 node update + pooling + (last block) dense head ----------------
__global__ void k_node2(const int* __restrict__ bidx,
                        const float* __restrict__ Ws, const float* __restrict__ Wn,
                        const float* __restrict__ b,
                        const float* __restrict__ Wd, const float* __restrict__ bd,
                        const float* __restrict__ Wo, const float* __restrict__ bo,
                        float* __restrict__ out) {
    gdep_launch();
    extern __shared__ float sm[];
    float* sWs = sm;            // 128*128 for this cout half
    float* sWn = sm + 16384;
    __shared__ float xs[2][128], as[2][128];
    __shared__ int lastFlag;
    int tid = threadIdx.x;
    int eh = tid >> 7, c = tid & 127;
    int h = blockIdx.x & 1, g = blockIdx.x >> 1;
    for (int i = tid; i < 16384; i += 256) {
        int k = i >> 7, cc = i & 127;
        sWs[i] = Ws[k * 256 + h * 128 + cc];
        sWn[i] = Wn[k * 256 + h * 128 + cc];
    }
    float bb = b[h * 128 + c];
    gdep_wait();
    __syncthreads();
    float pacc = 0.f;
    for (int e = 0; e < 8; e++) {
        int node = bidx[g * 16 + eh * 8 + e];
        xs[eh][c] = ((const float*)g_x2c)[g_slot1[node] * 128 + c];
        as[eh][c] = ((const float*)g_agg2)[g_slot2[node] * 128 + c];
        __syncthreads();
        float acc = bb;
#pragma unroll 16
        for (int k = 0; k < 128; k++)
            acc += xs[eh][k] * sWs[k * 128 + c] + as[eh][k] * sWn[k * 128 + c];
        pacc += fmaxf(acc, 0.f);
        __syncthreads();
    }
    atomicAdd(&g_pool[h * 128 + c], pacc);
    __threadfence();
    __syncthreads();
    if (tid == 0) lastFlag = (atomicAdd(&g_done, 1) == 127);
    __syncthreads();
    if (!lastFlag) return;

    // ---- dense head (last-arriving block) ----
    float* sp = sm;          // reuse smem
    float* sh = sm + 256;
    sp[tid] = g_pool[tid] * (1.f / NB);
    __syncthreads();
    float acc = bd[tid];
#pragma unroll 8
    for (int k = 0; k < 256; k++) acc += sp[k] * Wd[k * 256 + tid];
    sh[tid] = fmaxf(acc, 0.f);
    __syncthreads();
    if (tid < 12) {
        float o = bo[tid];
        for (int k = 0; k < 256; k++) o += sh[k] * Wo[k * 12 + tid];
        out[tid] = o + g_bsum[tid % 3] * (1.f / NB);
    }
}

// ---------------- host launch (PDL-chained) ----------------
template <typename... Args>
static void launch_pdl(void (*kern)(Args...), dim3 grid, dim3 block, size_t smem, Args... args) {
    cudaLaunchConfig_t cfg = {};
    cfg.gridDim = grid;
    cfg.blockDim = block;
    cfg.dynamicSmemBytes = smem;
    cfg.stream = 0;
    cudaLaunchAttribute attr[1];
    attr[0].id = cudaLaunchAttributeProgrammaticStreamSerialization;
    attr[0].val.programmaticStreamSerializationAllowed = 1;
    cfg.attrs = attr;
    cfg.numAttrs = 1;
    cudaLaunchKernelEx(&cfg, kern, args...);
}

extern "C" void kernel_launch(void* const* d_in, const int* in_sizes, int n_in,
                              void* d_out, int out_size) {
    const float* vs    = (const float*)d_in[0];
    const int*   edges = (const int*)d_in[1];
    const int*   bidx  = (const int*)d_in[2];
    int wb = n_in - 13;
    const float* Ws0 = (const float*)d_in[wb + 0];
    const float* Wn0 = (const float*)d_in[wb + 1];
    const float* b0  = (const float*)d_in[wb + 2];
    const float* Ws1 = (const float*)d_in[wb + 3];
    const float* Wn1 = (const float*)d_in[wb + 4];
    const float* b1  = (const float*)d_in[wb + 5];
    const float* Ws2 = (const float*)d_in[wb + 6];
    const float* Wn2 = (const float*)d_in[wb + 7];
    const float* b2  = (const float*)d_in[wb + 8];
    const float* Wd  = (const float*)d_in[wb + 9];
    const float* bd  = (const float*)d_in[wb + 10];
    const float* Wo  = (const float*)d_in[wb + 11];
    const float* bo  = (const float*)d_in[wb + 12];
    float* out = (float*)d_out;

    cudaFuncSetAttribute(k_node1, cudaFuncAttributeMaxDynamicSharedMemorySize, 65536);
    cudaFuncSetAttribute(k_node2, cudaFuncAttributeMaxDynamicSharedMemorySize, 131072);

    k_init<<<NBK, 256>>>(vs, bidx);
    launch_pdl(k_pass1,  dim3(EB), dim3(256), 0, edges);
    launch_pdl(k_pass2c, dim3(EB + NBK), dim3(256), 0, edges);
    launch_pdl(k_node0,  dim3((NW * 32 + 255) / 256), dim3(256), (size_t)0, Ws0, Wn0, b0);
    launch_pdl(k_edge1,  dim3(2368), dim3(256), 0);
    launch_pdl(k_node1,  dim3(444), dim3(256), (size_t)65536, Ws1, Wn1, b1);
    launch_pdl(k_edge2,  dim3(592), dim3(256), 0);
    launch_pdl(k_node2,  dim3(128), dim3(256), (size_t)131072,
               bidx, Ws2, Wn2, b2, Wd, bd, Wo, bo, out);
}

// round 16
// speedup vs baseline: 1.0182x; 1.0182x over previous
#include <cuda_runtime.h>

#define NN 100000
#define NE 300000
#define NB 1024
#define NW 3136           // bitmask words (ceil(NN/32), padded)
#define EB 1172           // edge blocks ((NE+255)/256)
#define NBK 391           // node blocks ((NN+255)/256)

// ---- PDL primitives (sm_90+) ----
__device__ __forceinline__ void gdep_launch() {
    asm volatile("griddepcontrol.launch_dependents;");
}
__device__ __forceinline__ void gdep_wait() {
    asm volatile("griddepcontrol.wait;" ::: "memory");
}

// ---------------- device scratch (static, 16B-aligned via float4) ----------------
__device__ float4 g_vs4[NN];              // positions padded to float4
__device__ float4 g_agg0[NN];             // position agg
__device__ float4 g_agg1[NN * 16];        // layer1 agg, compact by slot1
__device__ float4 g_agg2[NB * 32];        // layer2 agg, compact by slot2
__device__ float4 g_x1[NN * 16];          // layer0 out (written only where needed)
__device__ float4 g_x2c[NN * 32];         // layer1 out, compact by slot1
__device__ unsigned g_bmB[NW];            // boundary bitmask
__device__ unsigned g_bmN1[NW];           // N1 bitmask
__device__ unsigned g_bmN2[NW];           // after pass2c: "x1 needed" = N1 | N2
__device__ int g_slot1[NN];
__device__ int g_slot2[NN];
__device__ int g_list1[NN];               // slot1 -> node
__device__ int2 g_e1[NE];                 // active layer1 edges
__device__ int2 g_e2[NE];                 // active layer2 edges
__device__ int g_cnt1, g_cntE1, g_cntE2, g_done, g_done0;
__device__ float g_pool[256];
__device__ float g_bsum[3];

__device__ __forceinline__ int bm_get(const unsigned* bm, int n) {
    return (bm[n >> 5] >> (n & 31)) & 1;
}
__device__ __forceinline__ void bm_set(unsigned* bm, int n) {
    atomicOr(&bm[n >> 5], 1u << (n & 31));
}

// ---------------- init (+ last-block markB fusion) ----------------
__global__ void k_init(const float* __restrict__ vs, const int* __restrict__ bidx) {
    gdep_launch();
    int i = blockIdx.x * 256 + threadIdx.x;
    int tid = threadIdx.x;
    float4 z = make_float4(0.f, 0.f, 0.f, 0.f);
    if (i < NN) {
        g_agg0[i] = z;
        g_vs4[i] = make_float4(vs[3 * i], vs[3 * i + 1], vs[3 * i + 2], 0.f);
    }
    if (i < NW) { g_bmB[i] = 0; g_bmN1[i] = 0; g_bmN2[i] = 0; }
    if (i < NB * 32) g_agg2[i] = z;
    if (i < 256) g_pool[i] = 0.f;
    if (i < 3) g_bsum[i] = 0.f;
    if (i == 0) { g_cnt1 = 0; g_cntE1 = 0; g_cntE2 = 0; g_done = 0; }
    __shared__ int lastFlag;
    __threadfence();
    __syncthreads();
    if (tid == 0) lastFlag = (atomicAdd(&g_done0, 1) == NBK - 1);
    __syncthreads();
    if (!lastFlag) return;
    if (tid == 0) g_done0 = 0;            // self-reset for graph replay
    float s0 = 0.f, s1 = 0.f, s2 = 0.f;
    for (int j = tid; j < NB; j += 256) {
        int n = bidx[j];
        bm_set(g_bmB, n); bm_set(g_bmN1, n);
        g_slot2[n] = j;
        s0 += vs[3 * n]; s1 += vs[3 * n + 1]; s2 += vs[3 * n + 2];
    }
    atomicAdd(&g_bsum[0], s0);
    atomicAdd(&g_bsum[1], s1);
    atomicAdd(&g_bsum[2], s2);
}

// ---------------- pass 1: position agg + N1 mark + e2 emit ----------------
__global__ void k_pass1(const int* __restrict__ edges) {
    gdep_launch();
    int e = blockIdx.x * 256 + threadIdx.x;
    if (e >= NE) { gdep_wait(); return; }
    int s = edges[2 * e], d = edges[2 * e + 1];   // inputs: safe pre-wait
    gdep_wait();
    float4 ps = g_vs4[s];
    float4 pd = g_vs4[d];
    atomicAdd(&g_agg0[d], ps);
    atomicAdd(&g_agg0[s], pd);
    int bs = bm_get(g_bmB, s), bd = bm_get(g_bmB, d);
    if (bs | bd) {
        if (bd) bm_set(g_bmN1, s);
        if (bs) bm_set(g_bmN1, d);
        int p = atomicAdd(&g_cntE2, 1);
        g_e2[p] = make_int2(s | (bs << 30), d | (bd << 30));
    }
}

// ---------------- pass 2 (+ slot1 compaction in tail; tail ORs N1 into N2) ----------------
__global__ void k_pass2c(const int* __restrict__ edges) {
    gdep_launch();
    int bid = blockIdx.x;
    if (bid < EB) {
        int e = bid * 256 + threadIdx.x;
        if (e >= NE) { gdep_wait(); return; }
        int s = edges[2 * e], d = edges[2 * e + 1];   // pre-wait
        gdep_wait();
        int as = bm_get(g_bmN1, s), ad = bm_get(g_bmN1, d);
        if (as | ad) {
            if (ad) bm_set(g_bmN2, s);
            if (as) bm_set(g_bmN2, d);
            int p = atomicAdd(&g_cntE1, 1);
            g_e1[p] = make_int2(s | (as << 30), d | (ad << 30));
        }
    } else {
        gdep_wait();
        int i = (bid - EB) * 256 + threadIdx.x;
        if (i < NN) {
            if ((i & 31) == 0) {
                unsigned w = g_bmN1[i >> 5];
                if (w) atomicOr(&g_bmN2[i >> 5], w);
            }
            if (bm_get(g_bmN1, i)) {
                int p = atomicAdd(&g_cnt1, 1);
                g_slot1[i] = p; g_list1[p] = i;
                float4 z = make_float4(0.f, 0.f, 0.f, 0.f);
#pragma unroll
                for (int c = 0; c < 16; c++) g_agg1[p * 16 + c] = z;
            }
        }
    }
}

// ---------------- layer 0 node update: 4 warps/word, each owning an 8-bit sub-word ----------------
// Warp q of 4 owns bit positions [8q, 8q+8): walks ONLY its own set bits
// (no redundant iteration). Two half-warps alternate over those bits;
// 16 threads/node, 4 channels each, float4 weights.
__global__ void k_node0(const float* __restrict__ Ws, const float* __restrict__ Wn,
                        const float* __restrict__ b) {
    gdep_launch();
    int gwarp = (blockIdx.x * 256 + threadIdx.x) >> 5;
    int wid = gwarp >> 2;                 // word index
    int quarter = gwarp & 3;              // which 8-bit group of the word
    int lane = threadIdx.x & 31;
    int half = lane >> 4;
    int c4 = lane & 15;
    // prologue from input buffers only (PDL pre-wait)
    float4 w0 = ((const float4*)Ws)[c4];
    float4 w1 = ((const float4*)(Ws + 64))[c4];
    float4 w2 = ((const float4*)(Ws + 128))[c4];
    float4 n0 = ((const float4*)Wn)[c4];
    float4 n1 = ((const float4*)(Wn + 64))[c4];
    float4 n2 = ((const float4*)(Wn + 128))[c4];
    float4 bb = ((const float4*)b)[c4];
    gdep_wait();
    if (wid >= NW) return;
    unsigned sub = (g_bmN2[wid] >> (quarter * 8)) & 0xFFu;
    if (!sub) return;
    int base = (wid << 5) + quarter * 8;
    int idx = 0;
    while (sub) {
        int bit = __ffs(sub) - 1;
        sub &= sub - 1;
        if ((idx++ & 1) != half) continue;
        int node = base + bit;
        float4 p = g_vs4[node];
        float4 a = g_agg0[node];
        float4 r;
        r.x = fmaxf(bb.x + p.x*w0.x + p.y*w1.x + p.z*w2.x + a.x*n0.x + a.y*n1.x + a.z*n2.x, 0.f);
        r.y = fmaxf(bb.y + p.x*w0.y + p.y*w1.y + p.z*w2.y + a.x*n0.y + a.y*n1.y + a.z*n2.y, 0.f);
        r.z = fmaxf(bb.z + p.x*w0.z + p.y*w1.z + p.z*w2.z + a.x*n0.z + a.y*n1.z + a.z*n2.z, 0.f);
        r.w = fmaxf(bb.w + p.x*w0.w + p.y*w1.w + p.z*w2.w + a.x*n0.w + a.y*n1.w + a.z*n2.w, 0.f);
        g_x1[node * 16 + c4] = r;
    }
}

// ---------------- layer 1 edge aggregation ----------------
__global__ void k_edge1() {
    gdep_launch();
    gdep_wait();
    int tot = g_cntE1 << 4;
    int stride = gridDim.x * blockDim.x;
    for (int t = blockIdx.x * blockDim.x + threadIdx.x; t < tot; t += stride) {
        int ei = t >> 4, c4 = t & 15;
        int2 en = g_e1[ei];
        int s = en.x & 0x3FFFFFFF, sa = (unsigned)en.x >> 30;
        int d = en.y & 0x3FFFFFFF, da = (unsigned)en.y >> 30;
        if (da) atomicAdd(&g_agg1[g_slot1[d] * 16 + c4], g_x1[s * 16 + c4]);
        if (sa) atomicAdd(&g_agg1[g_slot1[s] * 16 + c4], g_x1[d * 16 + c4]);
    }
}

// ---------------- layer 1 node update: weights staged pre-wait ----------------
__global__ void k_node1(const float* __restrict__ Ws, const float* __restrict__ Wn,
                        const float* __restrict__ b) {
    gdep_launch();
    extern __shared__ float sm[];
    float* sWs = sm;            // 64*128
    float* sWn = sm + 8192;
    __shared__ float xs[2][64], as[2][64];
    int tid = threadIdx.x;
    int pair = tid >> 7, c = tid & 127;
    for (int i = tid; i < 8192; i += 256) { sWs[i] = Ws[i]; sWn[i] = Wn[i]; }
    float bc = b[c];
    gdep_wait();
    __syncthreads();
    int cnt = g_cnt1;
    for (int slot0 = blockIdx.x * 2; slot0 < cnt; slot0 += gridDim.x * 2) {
        int slot = slot0 + pair;
        bool act = slot < cnt;
        if (act && c < 128) {
            int node = g_list1[slot];
            if (c < 64) xs[pair][c] = ((const float*)g_x1)[node * 64 + c];
            else        as[pair][c - 64] = ((const float*)g_agg1)[slot * 64 + (c - 64)];
        }
        __syncthreads();
        if (act) {
            float acc = bc;
#pragma unroll 16
            for (int k = 0; k < 64; k++)
                acc += xs[pair][k] * sWs[k * 128 + c] + as[pair][k] * sWn[k * 128 + c];
            ((float*)g_x2c)[slot * 128 + c] = fmaxf(acc, 0.f);
        }
        __syncthreads();
    }
}

// ---------------- layer 2 edge aggregation ----------------
__global__ void k_edge2() {
    gdep_launch();
    gdep_wait();
    int tot = g_cntE2 << 5;
    int stride = gridDim.x * blockDim.x;
    for (int t = blockIdx.x * blockDim.x + threadIdx.x; t < tot; t += stride) {
        int ei = t >> 5, c4 = t & 31;
        int2 en = g_e2[ei];
        int s = en.x & 0x3FFFFFFF, bs = (unsigned)en.x >> 30;
        int d = en.y & 0x3FFFFFFF, bd = (unsigned)en.y >> 30;
        if (bd) atomicAdd(&g_agg2[g_slot2[d] * 32 + c4], g_x2c[g_slot1[s] * 32 + c4]);
        if (bs) atomicAdd(&g_agg2[g_slot2[s] * 32 + c4], g_x2c[g_slot1[d] * 32 + c4]);
    }
}

// ---------------- layer 2 node update + pooling + (last block) dense head ----------------
__global__ void k_node2(const int* __restrict__ bidx,
                        const float* __restrict__ Ws, const float* __restrict__ Wn,
                        const float* __restrict__ b,
                        const float* __restrict__ Wd, const float* __restrict__ bd,
                        const float* __restrict__ Wo, const float* __restrict__ bo,
                        float* __restrict__ out) {
    gdep_launch();
    extern __shared__ float sm[];
    float* sWs = sm;            // 128*128 for this cout half
    float* sWn = sm + 16384;
    __shared__ float xs[2][128], as[2][128];
    __shared__ int lastFlag;
    int tid = threadIdx.x;
    int eh = tid >> 7, c = tid & 127;
    int h = blockIdx.x & 1, g = blockIdx.x >> 1;
    for (int i = tid; i < 16384; i += 256) {
        int k = i >> 7, cc = i & 127;
        sWs[i] = Ws[k * 256 + h * 128 + cc];
        sWn[i] = Wn[k * 256 + h * 128 + cc];
    }
    float bb = b[h * 128 + c];
    gdep_wait();
    __syncthreads();
    float pacc = 0.f;
    for (int e = 0; e < 8; e++) {
        int node = bidx[g * 16 + eh * 8 + e];
        xs[eh][c] = ((const float*)g_x2c)[g_slot1[node] * 128 + c];
        as[eh][c] = ((const float*)g_agg2)[g_slot2[node] * 128 + c];
        __syncthreads();
        float acc = bb;
#pragma unroll 16
        for (int k = 0; k < 128; k++)
            acc += xs[eh][k] * sWs[k * 128 + c] + as[eh][k] * sWn[k * 128 + c];
        pacc += fmaxf(acc, 0.f);
        __syncthreads();
    }
    atomicAdd(&g_pool[h * 128 + c], pacc);
    __threadfence();
    __syncthreads();
    if (tid == 0) lastFlag = (atomicAdd(&g_done, 1) == 127);
    __syncthreads();
    if (!lastFlag) return;

    // ---- dense head (last-arriving block) ----
    float* sp = sm;          // reuse smem
    float* sh = sm + 256;
    sp[tid] = g_pool[tid] * (1.f / NB);
    __syncthreads();
    float acc = bd[tid];
#pragma unroll 8
    for (int k = 0; k < 256; k++) acc += sp[k] * Wd[k * 256 + tid];
    sh[tid] = fmaxf(acc, 0.f);
    __syncthreads();
    if (tid < 12) {
        float o = bo[tid];
        for (int k = 0; k < 256; k++) o += sh[k] * Wo[k * 12 + tid];
        out[tid] = o + g_bsum[tid % 3] * (1.f / NB);
    }
}

// ---------------- host launch (PDL-chained) ----------------
template <typename... Args>
static void launch_pdl(void (*kern)(Args...), dim3 grid, dim3 block, size_t smem, Args... args) {
    cudaLaunchConfig_t cfg = {};
    cfg.gridDim = grid;
    cfg.blockDim = block;
    cfg.dynamicSmemBytes = smem;
    cfg.stream = 0;
    cudaLaunchAttribute attr[1];
    attr[0].id = cudaLaunchAttributeProgrammaticStreamSerialization;
    attr[0].val.programmaticStreamSerializationAllowed = 1;
    cfg.attrs = attr;
    cfg.numAttrs = 1;
    cudaLaunchKernelEx(&cfg, kern, args...);
}

extern "C" void kernel_launch(void* const* d_in, const int* in_sizes, int n_in,
                              void* d_out, int out_size) {
    const float* vs    = (const float*)d_in[0];
    const int*   edges = (const int*)d_in[1];
    const int*   bidx  = (const int*)d_in[2];
    int wb = n_in - 13;
    const float* Ws0 = (const float*)d_in[wb + 0];
    const float* Wn0 = (const float*)d_in[wb + 1];
    const float* b0  = (const float*)d_in[wb + 2];
    const float* Ws1 = (const float*)d_in[wb + 3];
    const float* Wn1 = (const float*)d_in[wb + 4];
    const float* b1  = (const float*)d_in[wb + 5];
    const float* Ws2 = (const float*)d_in[wb + 6];
    const float* Wn2 = (const float*)d_in[wb + 7];
    const float* b2  = (const float*)d_in[wb + 8];
    const float* Wd  = (const float*)d_in[wb + 9];
    const float* bd  = (const float*)d_in[wb + 10];
    const float* Wo  = (const float*)d_in[wb + 11];
    const float* bo  = (const float*)d_in[wb + 12];
    float* out = (float*)d_out;

    cudaFuncSetAttribute(k_node1, cudaFuncAttributeMaxDynamicSharedMemorySize, 65536);
    cudaFuncSetAttribute(k_node2, cudaFuncAttributeMaxDynamicSharedMemorySize, 131072);

    k_init<<<NBK, 256>>>(vs, bidx);
    launch_pdl(k_pass1,  dim3(EB), dim3(256), 0, edges);
    launch_pdl(k_pass2c, dim3(EB + NBK), dim3(256), 0, edges);
    launch_pdl(k_node0,  dim3((NW * 4 * 32 + 255) / 256), dim3(256), (size_t)0, Ws0, Wn0, b0);
    launch_pdl(k_edge1,  dim3(2368), dim3(256), 0);
    launch_pdl(k_node1,  dim3(444), dim3(256), (size_t)65536, Ws1, Wn1, b1);
    launch_pdl(k_edge2,  dim3(592), dim3(256), 0);
    launch_pdl(k_node2,  dim3(128), dim3(256), (size_t)131072,
               bidx, Ws2, Wn2, b2, Wd, bd, Wo, bo, out);
}

// round 17
// speedup vs baseline: 1.0421x; 1.0235x over previous
#include <cuda_runtime.h>

#define NN 100000
#define NE 300000
#define NB 1024
#define NW 3136           // bitmask words (ceil(NN/32), padded)
#define EB 1172           // edge blocks ((NE+255)/256)
#define NBK 391           // node blocks ((NN+255)/256)
#define XQB 1568          // x1@N1 walk blocks (NW*4 warps / 8 warps-per-block)

// ---- PDL primitives (sm_90+) ----
__device__ __forceinline__ void gdep_launch() {
    asm volatile("griddepcontrol.launch_dependents;");
}
__device__ __forceinline__ void gdep_wait() {
    asm volatile("griddepcontrol.wait;" ::: "memory");
}

// ---------------- device scratch (static, 16B-aligned via float4) ----------------
__device__ float4 g_vs4[NN];              // positions padded to float4
__device__ float4 g_agg0[NN];             // position agg
__device__ float4 g_agg1[NN * 16];        // layer1 agg, compact by slot1
__device__ float4 g_agg2[NB * 32];        // layer2 agg, compact by slot2
__device__ float4 g_x1[NN * 16];          // layer0 out (materialized ONLY at N1 nodes)
__device__ float4 g_x2c[NN * 32];         // layer1 out, compact by slot1
__device__ unsigned g_bmB[NW];            // boundary bitmask
__device__ unsigned g_bmN1[NW];           // N1 bitmask
__device__ int g_slot1[NN];
__device__ int g_slot2[NN];
__device__ int g_list1[NN];               // slot1 -> node
__device__ int2 g_e1[NE];                 // active layer1 edges
__device__ int2 g_e2[NE];                 // active layer2 edges
__device__ int g_cnt1, g_cntE1, g_cntE2, g_done, g_done0;
__device__ float g_pool[256];
__device__ float g_bsum[3];

__device__ __forceinline__ int bm_get(const unsigned* bm, int n) {
    return (bm[n >> 5] >> (n & 31)) & 1;
}
__device__ __forceinline__ void bm_set(unsigned* bm, int n) {
    atomicOr(&bm[n >> 5], 1u << (n & 31));
}

// compute 4 channels (group c4) of x1 at a node from its pos/agg + layer0 weights
__device__ __forceinline__ float4 x1_compute(
    float4 p, float4 a,
    float4 w0, float4 w1, float4 w2,
    float4 n0, float4 n1, float4 n2, float4 bb)
{
    float4 r;
    r.x = fmaxf(bb.x + p.x*w0.x + p.y*w1.x + p.z*w2.x + a.x*n0.x + a.y*n1.x + a.z*n2.x, 0.f);
    r.y = fmaxf(bb.y + p.x*w0.y + p.y*w1.y + p.z*w2.y + a.x*n0.y + a.y*n1.y + a.z*n2.y, 0.f);
    r.z = fmaxf(bb.z + p.x*w0.z + p.y*w1.z + p.z*w2.z + a.x*n0.z + a.y*n1.z + a.z*n2.z, 0.f);
    r.w = fmaxf(bb.w + p.x*w0.w + p.y*w1.w + p.z*w2.w + a.x*n0.w + a.y*n1.w + a.z*n2.w, 0.f);
    return r;
}

// ---------------- init (+ last-block markB fusion) ----------------
__global__ void k_init(const float* __restrict__ vs, const int* __restrict__ bidx) {
    gdep_launch();
    int i = blockIdx.x * 256 + threadIdx.x;
    int tid = threadIdx.x;
    float4 z = make_float4(0.f, 0.f, 0.f, 0.f);
    if (i < NN) {
        g_agg0[i] = z;
        g_vs4[i] = make_float4(vs[3 * i], vs[3 * i + 1], vs[3 * i + 2], 0.f);
    }
    if (i < NW) { g_bmB[i] = 0; g_bmN1[i] = 0; }
    if (i < NB * 32) g_agg2[i] = z;
    if (i < 256) g_pool[i] = 0.f;
    if (i < 3) g_bsum[i] = 0.f;
    if (i == 0) { g_cnt1 = 0; g_cntE1 = 0; g_cntE2 = 0; g_done = 0; }
    __shared__ int lastFlag;
    __threadfence();
    __syncthreads();
    if (tid == 0) lastFlag = (atomicAdd(&g_done0, 1) == NBK - 1);
    __syncthreads();
    if (!lastFlag) return;
    if (tid == 0) g_done0 = 0;            // self-reset for graph replay
    float s0 = 0.f, s1 = 0.f, s2 = 0.f;
    for (int j = tid; j < NB; j += 256) {
        int n = bidx[j];
        bm_set(g_bmB, n); bm_set(g_bmN1, n);
        g_slot2[n] = j;
        s0 += vs[3 * n]; s1 += vs[3 * n + 1]; s2 += vs[3 * n + 2];
    }
    atomicAdd(&g_bsum[0], s0);
    atomicAdd(&g_bsum[1], s1);
    atomicAdd(&g_bsum[2], s2);
}

// ---------------- pass 1: position agg + N1 mark + e2 emit ----------------
__global__ void k_pass1(const int* __restrict__ edges) {
    gdep_launch();
    int e = blockIdx.x * 256 + threadIdx.x;
    if (e >= NE) { gdep_wait(); return; }
    int s = edges[2 * e], d = edges[2 * e + 1];   // inputs: safe pre-wait
    gdep_wait();
    float4 ps = g_vs4[s];
    float4 pd = g_vs4[d];
    atomicAdd(&g_agg0[d], ps);
    atomicAdd(&g_agg0[s], pd);
    int bs = bm_get(g_bmB, s), bd = bm_get(g_bmB, d);
    if (bs | bd) {
        if (bd) bm_set(g_bmN1, s);
        if (bs) bm_set(g_bmN1, d);
        int p = atomicAdd(&g_cntE2, 1);
        g_e2[p] = make_int2(s | (bs << 30), d | (bd << 30));
    }
}

// ---------------- pass 2: e1 emit | slot1 compaction | x1@N1 materialization ----------------
__global__ void k_pass2c(const int* __restrict__ edges,
                         const float* __restrict__ Ws, const float* __restrict__ Wn,
                         const float* __restrict__ b) {
    gdep_launch();
    int bid = blockIdx.x;
    if (bid < EB) {
        int e = bid * 256 + threadIdx.x;
        if (e >= NE) { gdep_wait(); return; }
        int s = edges[2 * e], d = edges[2 * e + 1];   // pre-wait
        gdep_wait();
        int as = bm_get(g_bmN1, s), ad = bm_get(g_bmN1, d);
        if (as | ad) {
            int p = atomicAdd(&g_cntE1, 1);
            g_e1[p] = make_int2(s | (as << 30), d | (ad << 30));
        }
    } else if (bid < EB + NBK) {
        gdep_wait();
        int i = (bid - EB) * 256 + threadIdx.x;
        if (i < NN && bm_get(g_bmN1, i)) {
            int p = atomicAdd(&g_cnt1, 1);
            g_slot1[i] = p; g_list1[p] = i;
            float4 z = make_float4(0.f, 0.f, 0.f, 0.f);
#pragma unroll
            for (int c = 0; c < 16; c++) g_agg1[p * 16 + c] = z;
        }
    } else {
        // x1 materialization at N1 nodes (for node1 self term): quarter-word walk
        int gw = (bid - EB - NBK) * 8 + (threadIdx.x >> 5);
        int wid = gw >> 2, quarter = gw & 3;
        int lane = threadIdx.x & 31;
        int half = lane >> 4;
        int c4 = lane & 15;
        float4 w0 = ((const float4*)Ws)[c4];
        float4 w1 = ((const float4*)(Ws + 64))[c4];
        float4 w2 = ((const float4*)(Ws + 128))[c4];
        float4 n0 = ((const float4*)Wn)[c4];
        float4 n1 = ((const float4*)(Wn + 64))[c4];
        float4 n2 = ((const float4*)(Wn + 128))[c4];
        float4 bb = ((const float4*)b)[c4];
        gdep_wait();
        if (wid >= NW) return;
        unsigned sub = (g_bmN1[wid] >> (quarter * 8)) & 0xFFu;
        if (!sub) return;
        int base = (wid << 5) + quarter * 8;
        int idx = 0;
        while (sub) {
            int bit = __ffs(sub) - 1;
            sub &= sub - 1;
            if ((idx++ & 1) != half) continue;
            int node = base + bit;
            g_x1[node * 16 + c4] =
                x1_compute(g_vs4[node], g_agg0[node], w0, w1, w2, n0, n1, n2, bb);
        }
    }
}

// ---------------- fused layer0+layer1 edge aggregation ----------------
// For each active edge direction, compute the SOURCE's x1 channels on the fly
// (from vs4/agg0 + layer0 weights) and atomically add into the dest's agg1 row.
__global__ void k_edge1f(const float* __restrict__ Ws, const float* __restrict__ Wn,
                         const float* __restrict__ b) {
    gdep_launch();
    int c4 = threadIdx.x & 15;            // t&15 == threadIdx.x&15 (stride mult of 256)
    float4 w0 = ((const float4*)Ws)[c4];
    float4 w1 = ((const float4*)(Ws + 64))[c4];
    float4 w2 = ((const float4*)(Ws + 128))[c4];
    float4 n0 = ((const float4*)Wn)[c4];
    float4 n1 = ((const float4*)(Wn + 64))[c4];
    float4 n2 = ((const float4*)(Wn + 128))[c4];
    float4 bb = ((const float4*)b)[c4];
    gdep_wait();
    int tot = g_cntE1 << 4;
    int stride = gridDim.x * blockDim.x;
    for (int t = blockIdx.x * blockDim.x + threadIdx.x; t < tot; t += stride) {
        int ei = t >> 4;
        int2 en = g_e1[ei];
        int s = en.x & 0x3FFFFFFF, sa = (unsigned)en.x >> 30;
        int d = en.y & 0x3FFFFFFF, da = (unsigned)en.y >> 30;
        if (da) {                          // x1[s] -> agg1[slot1[d]]
            float4 r = x1_compute(g_vs4[s], g_agg0[s], w0, w1, w2, n0, n1, n2, bb);
            atomicAdd(&g_agg1[g_slot1[d] * 16 + c4], r);
        }
        if (sa) {                          // x1[d] -> agg1[slot1[s]]
            float4 r = x1_compute(g_vs4[d], g_agg0[d], w0, w1, w2, n0, n1, n2, bb);
            atomicAdd(&g_agg1[g_slot1[s] * 16 + c4], r);
        }
    }
}

// ---------------- layer 1 node update: weights staged pre-wait ----------------
__global__ void k_node1(const float* __restrict__ Ws, const float* __restrict__ Wn,
                        const float* __restrict__ b) {
    gdep_launch();
    extern __shared__ float sm[];
    float* sWs = sm;            // 64*128
    float* sWn = sm + 8192;
    __shared__ float xs[2][64], as[2][64];
    int tid = threadIdx.x;
    int pair = tid >> 7, c = tid & 127;
    for (int i = tid; i < 8192; i += 256) { sWs[i] = Ws[i]; sWn[i] = Wn[i]; }
    float bc = b[c];
    gdep_wait();
    __syncthreads();
    int cnt = g_cnt1;
    for (int slot0 = blockIdx.x * 2; slot0 < cnt; slot0 += gridDim.x * 2) {
        int slot = slot0 + pair;
        bool act = slot < cnt;
        if (act && c < 128) {
            int node = g_list1[slot];
            if (c < 64) xs[pair][c] = ((const float*)g_x1)[node * 64 + c];
            else        as[pair][c - 64] = ((const float*)g_agg1)[slot * 64 + (c - 64)];
        }
        __syncthreads();
        if (act) {
            float acc = bc;
#pragma unroll 16
            for (int k = 0; k < 64; k++)
                acc += xs[pair][k] * sWs[k * 128 + c] + as[pair][k] * sWn[k * 128 + c];
            ((float*)g_x2c)[slot * 128 + c] = fmaxf(acc, 0.f);
        }
        __syncthreads();
    }
}

// ---------------- layer 2 edge aggregation ----------------
__global__ void k_edge2() {
    gdep_launch();
    gdep_wait();
    int tot = g_cntE2 << 5;
    int stride = gridDim.x * blockDim.x;
    for (int t = blockIdx.x * blockDim.x + threadIdx.x; t < tot; t += stride) {
        int ei = t >> 5, c4 = t & 31;
        int2 en = g_e2[ei];
        int s = en.x & 0x3FFFFFFF, bs = (unsigned)en.x >> 30;
        int d = en.y & 0x3FFFFFFF, bd = (unsigned)en.y >> 30;
        if (bd) atomicAdd(&g_agg2[g_slot2[d] * 32 + c4], g_x2c[g_slot1[s] * 32 + c4]);
        if (bs) atomicAdd(&g_agg2[g_slot2[s] * 32 + c4], g_x2c[g_slot1[d] * 32 + c4]);
    }
}

// ---------------- layer 2 node update + pooling + (last block) dense head ----------------
__global__ void k_node2(const int* __restrict__ bidx,
                        const float* __restrict__ Ws, const float* __restrict__ Wn,
                        const float* __restrict__ b,
                        const float* __restrict__ Wd, const float* __restrict__ bd,
                        const float* __restrict__ Wo, const float* __restrict__ bo,
                        float* __restrict__ out) {
    gdep_launch();
    extern __shared__ float sm[];
    float* sWs = sm;            // 128*128 for this cout half
    float* sWn = sm + 16384;
    __shared__ float xs[2][128], as[2][128];
    __shared__ int lastFlag;
    int tid = threadIdx.x;
    int eh = tid >> 7, c = tid & 127;
    int h = blockIdx.x & 1, g = blockIdx.x >> 1;
    for (int i = tid; i < 16384; i += 256) {
        int k = i >> 7, cc = i & 127;
        sWs[i] = Ws[k * 256 + h * 128 + cc];
        sWn[i] = Wn[k * 256 + h * 128 + cc];
    }
    float bb = b[h * 128 + c];
    gdep_wait();
    __syncthreads();
    float pacc = 0.f;
    for (int e = 0; e < 8; e++) {
        int node = bidx[g * 16 + eh * 8 + e];
        xs[eh][c] = ((const float*)g_x2c)[g_slot1[node] * 128 + c];
        as[eh][c] = ((const float*)g_agg2)[g_slot2[node] * 128 + c];
        __syncthreads();
        float acc = bb;
#pragma unroll 16
        for (int k = 0; k < 128; k++)
            acc += xs[eh][k] * sWs[k * 128 + c] + as[eh][k] * sWn[k * 128 + c];
        pacc += fmaxf(acc, 0.f);
        __syncthreads();
    }
    atomicAdd(&g_pool[h * 128 + c], pacc);
    __threadfence();
    __syncthreads();
    if (tid == 0) lastFlag = (atomicAdd(&g_done, 1) == 127);
    __syncthreads();
    if (!lastFlag) return;

    // ---- dense head (last-arriving block) ----
    float* sp = sm;          // reuse smem
    float* sh = sm + 256;
    sp[tid] = g_pool[tid] * (1.f / NB);
    __syncthreads();
    float acc = bd[tid];
#pragma unroll 8
    for (int k = 0; k < 256; k++) acc += sp[k] * Wd[k * 256 + tid];
    sh[tid] = fmaxf(acc, 0.f);
    __syncthreads();
    if (tid < 12) {
        float o = bo[tid];
        for (int k = 0; k < 256; k++) o += sh[k] * Wo[k * 12 + tid];
        out[tid] = o + g_bsum[tid % 3] * (1.f / NB);
    }
}

// ---------------- host launch (PDL-chained) ----------------
template <typename... Args>
static void launch_pdl(void (*kern)(Args...), dim3 grid, dim3 block, size_t smem, Args... args) {
    cudaLaunchConfig_t cfg = {};
    cfg.gridDim = grid;
    cfg.blockDim = block;
    cfg.dynamicSmemBytes = smem;
    cfg.stream = 0;
    cudaLaunchAttribute attr[1];
    attr[0].id = cudaLaunchAttributeProgrammaticStreamSerialization;
    attr[0].val.programmaticStreamSerializationAllowed = 1;
    cfg.attrs = attr;
    cfg.numAttrs = 1;
    cudaLaunchKernelEx(&cfg, kern, args...);
}

extern "C" void kernel_launch(void* const* d_in, const int* in_sizes, int n_in,
                              void* d_out, int out_size) {
    const float* vs    = (const float*)d_in[0];
    const int*   edges = (const int*)d_in[1];
    const int*   bidx  = (const int*)d_in[2];
    int wb = n_in - 13;
    const float* Ws0 = (const float*)d_in[wb + 0];
    const float* Wn0 = (const float*)d_in[wb + 1];
    const float* b0  = (const float*)d_in[wb + 2];
    const float* Ws1 = (const float*)d_in[wb + 3];
    const float* Wn1 = (const float*)d_in[wb + 4];
    const float* b1  = (const float*)d_in[wb + 5];
    const float* Ws2 = (const float*)d_in[wb + 6];
    const float* Wn2 = (const float*)d_in[wb + 7];
    const float* b2  = (const float*)d_in[wb + 8];
    const float* Wd  = (const float*)d_in[wb + 9];
    const float* bd  = (const float*)d_in[wb + 10];
    const float* Wo  = (const float*)d_in[wb + 11];
    const float* bo  = (const float*)d_in[wb + 12];
    float* out = (float*)d_out;

    cudaFuncSetAttribute(k_node1, cudaFuncAttributeMaxDynamicSharedMemorySize, 65536);
    cudaFuncSetAttribute(k_node2, cudaFuncAttributeMaxDynamicSharedMemorySize, 131072);

    k_init<<<NBK, 256>>>(vs, bidx);
    launch_pdl(k_pass1,  dim3(EB), dim3(256), 0, edges);
    launch_pdl(k_pass2c, dim3(EB + NBK + XQB), dim3(256), (size_t)0, edges, Ws0, Wn0, b0);
    launch_pdl(k_edge1f, dim3(2368), dim3(256), (size_t)0, Ws0, Wn0, b0);
    launch_pdl(k_node1,  dim3(444), dim3(256), (size_t)65536, Ws1, Wn1, b1);
    launch_pdl(k_edge2,  dim3(592), dim3(256), 0);
    launch_pdl(k_node2,  dim3(128), dim3(256), (size_t)131072,
               bidx, Ws2, Wn2, b2, Wd, bd, Wo, bo, out);
}